// round 1
// baseline (speedup 1.0000x reference)
#include <cuda_runtime.h>

#define HDIM 64
#define BM 128
#define BN 64
#define PAD 68
#define SEQ 4096

__global__ __launch_bounds__(128, 2)
void attn_fp32_flash(const float* __restrict__ q, const float* __restrict__ k,
                     const float* __restrict__ v, float* __restrict__ out)
{
    // 8704 floats = 34816 B, reused: Q staging (128xPAD) then Ks|Vs (each 64xPAD)
    __shared__ __align__(16) float smem[BM * PAD];
    float* Ks = smem;               // [BN][PAD], row jj = key j0+jj
    float* Vs = smem + BN * PAD;    // [BN][PAD]

    const int tid = threadIdx.x;
    const int qb  = blockIdx.x;     // query block (128 rows)
    const int h   = blockIdx.y;     // head
    const int qi  = qb * BM + tid;  // this thread's query row

    const float* qh = q + (size_t)h * SEQ * HDIM;
    const float* kh = k + (size_t)h * HDIM * SEQ;   // [D][S]
    const float* vh = v + (size_t)h * SEQ * HDIM;

    // ---- stage Q block coalesced via smem, then own row -> registers ----
    {
        const float4* qg = (const float4*)(qh + (size_t)qb * BM * HDIM);
        for (int i4 = tid; i4 < BM * (HDIM / 4); i4 += 128) {
            int row = i4 >> 4, d4 = i4 & 15;
            *(float4*)&smem[row * PAD + 4 * d4] = qg[row * 16 + d4];
        }
    }
    __syncthreads();
    float4 qr[16];
    #pragma unroll
    for (int d4 = 0; d4 < 16; d4++)
        qr[d4] = *(const float4*)&smem[tid * PAD + 4 * d4];
    __syncthreads();

    float acc[HDIM];
    #pragma unroll
    for (int d = 0; d < HDIM; d++) acc[d] = 0.f;
    float m = -1e30f, l = 0.f;

    const int ntiles = qb * 2 + 2;  // covers keys [0, qb*128+128)
    for (int t = 0; t < ntiles; t++) {
        const int j0 = t * BN;

        // load K tile: global [d][s] coalesced in s -> Ks[jj][d]
        for (int idx = tid; idx < BN * HDIM; idx += 128) {
            int jj = idx & (BN - 1), d = idx >> 6;
            Ks[jj * PAD + d] = kh[(size_t)d * SEQ + j0 + jj];
        }
        // load V tile: contiguous float4
        {
            const float4* vg = (const float4*)(vh + (size_t)j0 * HDIM);
            for (int i4 = tid; i4 < BN * (HDIM / 4); i4 += 128) {
                int jj = i4 >> 4, d4 = i4 & 15;
                *(float4*)&Vs[jj * PAD + 4 * d4] = vg[i4];
            }
        }
        __syncthreads();

        #pragma unroll
        for (int c = 0; c < BN / 16; c++) {
            const int jb = j0 + c * 16;
            if (jb <= qi) {               // chunk has at least one unmasked key
                float s[16];
                #pragma unroll
                for (int jj = 0; jj < 16; jj++) {
                    const float4* kr = (const float4*)&Ks[(c * 16 + jj) * PAD];
                    float sum = 0.f;
                    #pragma unroll
                    for (int d4 = 0; d4 < 16; d4++) {
                        float4 kv = kr[d4];   // uniform addr -> smem broadcast
                        sum += qr[d4].x * kv.x + qr[d4].y * kv.y
                             + qr[d4].z * kv.z + qr[d4].w * kv.w;
                    }
                    // scale 1/sqrt(64); causal mask -> -1e30 (exp underflows to 0)
                    s[jj] = (jb + jj <= qi) ? sum * 0.125f : -1e30f;
                }
                float mc = s[0];
                #pragma unroll
                for (int jj = 1; jj < 16; jj++) mc = fmaxf(mc, s[jj]);
                const float mnew = fmaxf(m, mc);
                const float corr = __expf(m - mnew);  // m=-1e30 init -> corr=0
                l *= corr;
                #pragma unroll
                for (int d = 0; d < HDIM; d++) acc[d] *= corr;
                #pragma unroll
                for (int jj = 0; jj < 16; jj++) {
                    const float p = __expf(s[jj] - mnew);
                    l += p;
                    const float4* vr = (const float4*)&Vs[(c * 16 + jj) * PAD];
                    #pragma unroll
                    for (int d4 = 0; d4 < 16; d4++) {
                        float4 vv = vr[d4];
                        acc[4 * d4 + 0] += p * vv.x;
                        acc[4 * d4 + 1] += p * vv.y;
                        acc[4 * d4 + 2] += p * vv.z;
                        acc[4 * d4 + 3] += p * vv.w;
                    }
                }
                m = mnew;
            }
        }
        __syncthreads();
    }

    const float inv = 1.f / l;   // l > 0: diagonal key always present
    float* og = out + ((size_t)h * SEQ + qi) * HDIM;
    #pragma unroll
    for (int d4 = 0; d4 < 16; d4++) {
        float4 o;
        o.x = acc[4 * d4 + 0] * inv;
        o.y = acc[4 * d4 + 1] * inv;
        o.z = acc[4 * d4 + 2] * inv;
        o.w = acc[4 * d4 + 3] * inv;
        *(float4*)&og[4 * d4] = o;
    }
}

extern "C" void kernel_launch(void* const* d_in, const int* in_sizes, int n_in,
                              void* d_out, int out_size)
{
    const float* q = (const float*)d_in[0];
    const float* k = (const float*)d_in[1];
    const float* v = (const float*)d_in[2];
    float* out = (float*)d_out;

    dim3 grid(SEQ / BM, 16, 1);   // 32 query blocks x 16 heads
    attn_fp32_flash<<<grid, 128>>>(q, k, v, out);
}

// round 2
// speedup vs baseline: 2.1768x; 2.1768x over previous
#include <cuda_runtime.h>
#include <cstdint>

#define SEQ 4096
#define HDIM 64
#define BM 64
#define BN 32

struct SmemT {
    float2 khl[64][34];   // K tile, (hi,lo) per element: [d][jj]
    float2 vhl[32][66];   // V tile, (hi,lo): [jj][d]
    float  p[64][34];     // P tile fp32: [local row][jj]
};
union SmemU {
    SmemT s;
    float qstage[64][68];
};

__device__ __forceinline__ uint32_t f2tf(float f) {
    uint32_t u; asm("cvt.rna.tf32.f32 %0, %1;" : "=r"(u) : "f"(f)); return u;
}
__device__ __forceinline__ void split_tf32(float f, uint32_t& hi, uint32_t& lo) {
    hi = f2tf(f);
    lo = f2tf(f - __uint_as_float(hi));
}
__device__ __forceinline__ void mma8(float* c, uint32_t a0, uint32_t a1, uint32_t a2, uint32_t a3,
                                     uint32_t b0, uint32_t b1) {
    asm volatile("mma.sync.aligned.m16n8k8.row.col.f32.tf32.tf32.f32 "
                 "{%0,%1,%2,%3}, {%4,%5,%6,%7}, {%8,%9}, {%0,%1,%2,%3};"
                 : "+f"(c[0]), "+f"(c[1]), "+f"(c[2]), "+f"(c[3])
                 : "r"(a0), "r"(a1), "r"(a2), "r"(a3), "r"(b0), "r"(b1));
}

__global__ __launch_bounds__(128, 2)
void attn_tf32_flash(const float* __restrict__ q, const float* __restrict__ k,
                     const float* __restrict__ v, float* __restrict__ out)
{
    __shared__ __align__(16) SmemU sm;

    const int tid  = threadIdx.x;
    const int lane = tid & 31;
    const int w    = tid >> 5;
    const int qb   = (int)gridDim.x - 1 - (int)blockIdx.x;  // heavy blocks first
    const int h    = blockIdx.y;
    const int r    = lane >> 2;   // 0..7
    const int c    = lane & 3;    // 0..3

    const float* qh = q + (size_t)h * SEQ * HDIM;
    const float* kh = k + (size_t)h * HDIM * SEQ;   // [D][S]
    const float* vh = v + (size_t)h * SEQ * HDIM;

    // ---- stage Q block [64][64] coalesced, then fragments (scale 1/8 folded in) ----
    {
        const float4* qg = (const float4*)(qh + (size_t)qb * BM * HDIM);
        for (int i4 = tid; i4 < BM * (HDIM / 4); i4 += 128) {
            int row = i4 >> 4, d4 = i4 & 15;
            *(float4*)&sm.qstage[row][4 * d4] = qg[i4];
        }
    }
    __syncthreads();

    uint32_t qhi[32], qlo[32];
    {
        const int r0 = w * 16 + r, r1 = r0 + 8;
        #pragma unroll
        for (int kt = 0; kt < 8; kt++) {
            split_tf32(sm.qstage[r0][8 * kt + c]     * 0.125f, qhi[4 * kt + 0], qlo[4 * kt + 0]);
            split_tf32(sm.qstage[r1][8 * kt + c]     * 0.125f, qhi[4 * kt + 1], qlo[4 * kt + 1]);
            split_tf32(sm.qstage[r0][8 * kt + c + 4] * 0.125f, qhi[4 * kt + 2], qlo[4 * kt + 2]);
            split_tf32(sm.qstage[r1][8 * kt + c + 4] * 0.125f, qhi[4 * kt + 3], qlo[4 * kt + 3]);
        }
    }
    __syncthreads();   // done with qstage; smem becomes K/V/P

    float oacc[8][4];
    #pragma unroll
    for (int nt = 0; nt < 8; nt++)
        #pragma unroll
        for (int i = 0; i < 4; i++) oacc[nt][i] = 0.f;
    float m0 = -1e30f, m1 = -1e30f, l0 = 0.f, l1 = 0.f;

    const int row0 = qb * 64 + w * 16 + r;   // this thread's global rows
    const int row1 = row0 + 8;
    const int lr0  = w * 16 + r;             // local rows for P smem
    const int lr1  = lr0 + 8;

    const int ntile = 2 * (qb + 1);
    for (int t = 0; t < ntile; t++) {
        const int j0 = 32 * t;

        // ---- stage K tile: [d][jj] with tf32 hi/lo split ----
        for (int i4 = tid; i4 < 512; i4 += 128) {
            int d = i4 >> 3, j4 = (i4 & 7) * 4;
            float4 g = *(const float4*)&kh[(size_t)d * SEQ + j0 + j4];
            uint32_t h0,l0_,h1,l1_,h2,l2_,h3,l3_;
            split_tf32(g.x, h0, l0_); split_tf32(g.y, h1, l1_);
            split_tf32(g.z, h2, l2_); split_tf32(g.w, h3, l3_);
            *(float4*)&sm.s.khl[d][j4]     = make_float4(__uint_as_float(h0), __uint_as_float(l0_),
                                                         __uint_as_float(h1), __uint_as_float(l1_));
            *(float4*)&sm.s.khl[d][j4 + 2] = make_float4(__uint_as_float(h2), __uint_as_float(l2_),
                                                         __uint_as_float(h3), __uint_as_float(l3_));
        }
        // ---- stage V tile: [jj][d] hi/lo ----
        for (int i4 = tid; i4 < 512; i4 += 128) {
            int jj = i4 >> 4, d4 = (i4 & 15) * 4;
            float4 g = *(const float4*)&vh[(size_t)(j0 + jj) * HDIM + d4];
            uint32_t h0,l0_,h1,l1_,h2,l2_,h3,l3_;
            split_tf32(g.x, h0, l0_); split_tf32(g.y, h1, l1_);
            split_tf32(g.z, h2, l2_); split_tf32(g.w, h3, l3_);
            *(float4*)&sm.s.vhl[jj][d4]     = make_float4(__uint_as_float(h0), __uint_as_float(l0_),
                                                          __uint_as_float(h1), __uint_as_float(l1_));
            *(float4*)&sm.s.vhl[jj][d4 + 2] = make_float4(__uint_as_float(h2), __uint_as_float(l2_),
                                                          __uint_as_float(h3), __uint_as_float(l3_));
        }
        __syncthreads();

        const bool active = (j0 <= qb * 64 + w * 16 + 15);
        if (active) {
            // ---- S = Q K^T (3xTF32) ----
            float sacc[4][4];
            #pragma unroll
            for (int nt = 0; nt < 4; nt++)
                #pragma unroll
                for (int i = 0; i < 4; i++) sacc[nt][i] = 0.f;

            #pragma unroll
            for (int nt = 0; nt < 4; nt++) {
                #pragma unroll
                for (int kt = 0; kt < 8; kt++) {
                    float2 p0 = sm.s.khl[8 * kt + c][8 * nt + r];
                    float2 p1 = sm.s.khl[8 * kt + c + 4][8 * nt + r];
                    uint32_t bh0 = __float_as_uint(p0.x), bl0 = __float_as_uint(p0.y);
                    uint32_t bh1 = __float_as_uint(p1.x), bl1 = __float_as_uint(p1.y);
                    mma8(sacc[nt], qlo[4*kt], qlo[4*kt+1], qlo[4*kt+2], qlo[4*kt+3], bh0, bh1);
                    mma8(sacc[nt], qhi[4*kt], qhi[4*kt+1], qhi[4*kt+2], qhi[4*kt+3], bl0, bl1);
                    mma8(sacc[nt], qhi[4*kt], qhi[4*kt+1], qhi[4*kt+2], qhi[4*kt+3], bh0, bh1);
                }
            }

            // ---- causal mask (diagonal tiles only, warp-uniform guard) ----
            if (j0 + 31 > qb * 64 + w * 16) {
                #pragma unroll
                for (int nt = 0; nt < 4; nt++) {
                    int col = j0 + 8 * nt + 2 * c;
                    if (col     > row0) sacc[nt][0] = -1e30f;
                    if (col + 1 > row0) sacc[nt][1] = -1e30f;
                    if (col     > row1) sacc[nt][2] = -1e30f;
                    if (col + 1 > row1) sacc[nt][3] = -1e30f;
                }
            }

            // ---- online softmax ----
            float mx0 = sacc[0][0], mx1 = sacc[0][2];
            #pragma unroll
            for (int nt = 0; nt < 4; nt++) {
                mx0 = fmaxf(mx0, fmaxf(sacc[nt][0], sacc[nt][1]));
                mx1 = fmaxf(mx1, fmaxf(sacc[nt][2], sacc[nt][3]));
            }
            mx0 = fmaxf(mx0, __shfl_xor_sync(0xffffffffu, mx0, 1));
            mx0 = fmaxf(mx0, __shfl_xor_sync(0xffffffffu, mx0, 2));
            mx1 = fmaxf(mx1, __shfl_xor_sync(0xffffffffu, mx1, 1));
            mx1 = fmaxf(mx1, __shfl_xor_sync(0xffffffffu, mx1, 2));

            const float nm0 = fmaxf(m0, mx0), nm1 = fmaxf(m1, mx1);
            const float cor0 = __expf(m0 - nm0), cor1 = __expf(m1 - nm1);
            l0 *= cor0; l1 *= cor1;
            #pragma unroll
            for (int nt = 0; nt < 8; nt++) {
                oacc[nt][0] *= cor0; oacc[nt][1] *= cor0;
                oacc[nt][2] *= cor1; oacc[nt][3] *= cor1;
            }
            float sum0 = 0.f, sum1 = 0.f;
            #pragma unroll
            for (int nt = 0; nt < 4; nt++) {
                float p00 = __expf(sacc[nt][0] - nm0);
                float p01 = __expf(sacc[nt][1] - nm0);
                float p10 = __expf(sacc[nt][2] - nm1);
                float p11 = __expf(sacc[nt][3] - nm1);
                sum0 += p00 + p01; sum1 += p10 + p11;
                *(float2*)&sm.s.p[lr0][8 * nt + 2 * c] = make_float2(p00, p01);
                *(float2*)&sm.s.p[lr1][8 * nt + 2 * c] = make_float2(p10, p11);
            }
            sum0 += __shfl_xor_sync(0xffffffffu, sum0, 1);
            sum0 += __shfl_xor_sync(0xffffffffu, sum0, 2);
            sum1 += __shfl_xor_sync(0xffffffffu, sum1, 1);
            sum1 += __shfl_xor_sync(0xffffffffu, sum1, 2);
            l0 += sum0; l1 += sum1;
            m0 = nm0; m1 = nm1;
            __syncwarp();

            // ---- O += P V (3xTF32) ----
            #pragma unroll
            for (int jt = 0; jt < 4; jt++) {
                uint32_t ah[4], al[4];
                split_tf32(sm.s.p[lr0][8 * jt + c],     ah[0], al[0]);
                split_tf32(sm.s.p[lr1][8 * jt + c],     ah[1], al[1]);
                split_tf32(sm.s.p[lr0][8 * jt + c + 4], ah[2], al[2]);
                split_tf32(sm.s.p[lr1][8 * jt + c + 4], ah[3], al[3]);
                #pragma unroll
                for (int nt = 0; nt < 8; nt++) {
                    float2 p0 = sm.s.vhl[8 * jt + c][8 * nt + r];
                    float2 p1 = sm.s.vhl[8 * jt + c + 4][8 * nt + r];
                    uint32_t bh0 = __float_as_uint(p0.x), bl0 = __float_as_uint(p0.y);
                    uint32_t bh1 = __float_as_uint(p1.x), bl1 = __float_as_uint(p1.y);
                    mma8(oacc[nt], al[0], al[1], al[2], al[3], bh0, bh1);
                    mma8(oacc[nt], ah[0], ah[1], ah[2], ah[3], bl0, bl1);
                    mma8(oacc[nt], ah[0], ah[1], ah[2], ah[3], bh0, bh1);
                }
            }
        }
        __syncthreads();
    }

    // ---- epilogue ----
    const float inv0 = 1.f / l0, inv1 = 1.f / l1;
    float* o0 = out + ((size_t)h * SEQ + row0) * HDIM;
    float* o1 = out + ((size_t)h * SEQ + row1) * HDIM;
    #pragma unroll
    for (int nt = 0; nt < 8; nt++) {
        int col = 8 * nt + 2 * c;
        *(float2*)&o0[col] = make_float2(oacc[nt][0] * inv0, oacc[nt][1] * inv0);
        *(float2*)&o1[col] = make_float2(oacc[nt][2] * inv1, oacc[nt][3] * inv1);
    }
}

extern "C" void kernel_launch(void* const* d_in, const int* in_sizes, int n_in,
                              void* d_out, int out_size)
{
    const float* q = (const float*)d_in[0];
    const float* k = (const float*)d_in[1];
    const float* v = (const float*)d_in[2];
    float* out = (float*)d_out;

    dim3 grid(SEQ / BM, 16, 1);   // 64 query blocks x 16 heads
    attn_tf32_flash<<<grid, 128>>>(q, k, v, out);
}

// round 4
// speedup vs baseline: 9.3623x; 4.3010x over previous
#include <cuda_runtime.h>
#include <cstdint>

#define SEQ 4096
#define HDIM 64

struct __align__(16) Smem {
    uint2 khi[4][32][4];   // K hi frags: [k16-chunk][key n][c] -> (word_c, word_{c+4})
    uint2 klo[4][32][4];
    uint2 vhi[2][64][4];   // V frags: [key16-chunk][d n][c]
    uint2 vlo[2][64][4];
    union {
        struct { float kraw[64][32]; float vraw[32][64]; } r;
        float qstage[64][72];
    } u;
};

__device__ __forceinline__ uint32_t pack2(float e_lo, float e_hi) {
    uint32_t r;
    asm("cvt.rn.bf16x2.f32 %0, %1, %2;" : "=r"(r) : "f"(e_hi), "f"(e_lo));
    return r;
}
__device__ __forceinline__ void split2(float e0, float e1, uint32_t& h, uint32_t& l) {
    h = pack2(e0, e1);
    float h0 = __uint_as_float(h << 16);
    float h1 = __uint_as_float(h & 0xffff0000u);
    l = pack2(e0 - h0, e1 - h1);
}
__device__ __forceinline__ void mma_bf16(float* c, const uint32_t* a, uint32_t b0, uint32_t b1) {
    asm volatile("mma.sync.aligned.m16n8k16.row.col.f32.bf16.bf16.f32 "
                 "{%0,%1,%2,%3}, {%4,%5,%6,%7}, {%8,%9}, {%0,%1,%2,%3};"
                 : "+f"(c[0]), "+f"(c[1]), "+f"(c[2]), "+f"(c[3])
                 : "r"(a[0]), "r"(a[1]), "r"(a[2]), "r"(a[3]), "r"(b0), "r"(b1));
}
__device__ __forceinline__ void cpa16(uint32_t s, const float* g) {
    asm volatile("cp.async.cg.shared.global [%0], [%1], 16;" :: "r"(s), "l"(g));
}

__global__ __launch_bounds__(128, 3)
void attn_bf16x3_flash(const float* __restrict__ q, const float* __restrict__ k,
                       const float* __restrict__ v, float* __restrict__ out)
{
    __shared__ Smem sm;
    const int tid  = threadIdx.x;
    const int lane = tid & 31;
    const int w    = tid >> 5;
    const int qb   = (int)gridDim.x - 1 - (int)blockIdx.x;   // heavy blocks first
    const int h    = blockIdx.y;
    const int r    = lane >> 2;   // 0..7
    const int c    = lane & 3;    // 0..3

    const float* qh = q + (size_t)h * SEQ * HDIM;
    const float* kh = k + (size_t)h * HDIM * SEQ;            // [D][S]
    const float* vh = v + (size_t)h * SEQ * HDIM;

    // ---- stage Q block [64][64], build bf16 hi/lo A-fragments (scale folded) ----
    {
        const float4* qg = (const float4*)(qh + (size_t)qb * 64 * HDIM);
        for (int i4 = tid; i4 < 64 * 16; i4 += 128) {
            int row = i4 >> 4, d4 = i4 & 15;
            *(float4*)&sm.u.qstage[row][4 * d4] = qg[i4];
        }
    }
    __syncthreads();
    uint32_t qhi[4][4], qlo[4][4];
    {
        const int r0 = w * 16 + r, r1 = r0 + 8;
        #pragma unroll
        for (int kt = 0; kt < 4; kt++) {
            float2 x0 = *(float2*)&sm.u.qstage[r0][16 * kt + 2 * c];
            float2 x1 = *(float2*)&sm.u.qstage[r1][16 * kt + 2 * c];
            float2 x2 = *(float2*)&sm.u.qstage[r0][16 * kt + 2 * c + 8];
            float2 x3 = *(float2*)&sm.u.qstage[r1][16 * kt + 2 * c + 8];
            split2(x0.x * 0.125f, x0.y * 0.125f, qhi[kt][0], qlo[kt][0]);
            split2(x1.x * 0.125f, x1.y * 0.125f, qhi[kt][1], qlo[kt][1]);
            split2(x2.x * 0.125f, x2.y * 0.125f, qhi[kt][2], qlo[kt][2]);
            split2(x3.x * 0.125f, x3.y * 0.125f, qhi[kt][3], qlo[kt][3]);
        }
    }
    __syncthreads();

    const uint32_t kraw_s = (uint32_t)__cvta_generic_to_shared(&sm.u.r.kraw[0][0]);
    const uint32_t vraw_s = (uint32_t)__cvta_generic_to_shared(&sm.u.r.vraw[0][0]);

    float oacc[8][4];
    #pragma unroll
    for (int nt = 0; nt < 8; nt++)
        #pragma unroll
        for (int i = 0; i < 4; i++) oacc[nt][i] = 0.f;
    float m0 = -1e30f, m1 = -1e30f, l0 = 0.f, l1 = 0.f;

    const int row0 = qb * 64 + w * 16 + r;
    const int row1 = row0 + 8;
    const int vjt  = tid >> 6;        // convert-phase V ownership
    const int vn   = tid & 63;

    auto stage = [&](int t) {
        const int j0 = 32 * t;
        #pragma unroll
        for (int it = 0; it < 4; it++) {
            int i4 = tid + 128 * it;
            int d = i4 >> 3, j4 = (i4 & 7) * 4;
            cpa16(kraw_s + (uint32_t)(d * 32 + j4) * 4u, kh + (size_t)d * SEQ + j0 + j4);
        }
        #pragma unroll
        for (int it = 0; it < 4; it++) {
            int i4 = tid + 128 * it;
            int jj = i4 >> 4, d4 = (i4 & 15) * 4;
            cpa16(vraw_s + (uint32_t)(jj * 64 + d4) * 4u, vh + (size_t)(j0 + jj) * HDIM + d4);
        }
        asm volatile("cp.async.commit_group;");
    };

    auto convert = [&]() {
        {   // K: thread owns (chunk kt=w, key n=lane); reads 16 consecutive d
            float f[16];
            #pragma unroll
            for (int kk = 0; kk < 16; kk++) f[kk] = sm.u.r.kraw[16 * w + kk][lane];
            uint32_t wh[8], wl[8];
            #pragma unroll
            for (int x = 0; x < 8; x++) split2(f[2 * x], f[2 * x + 1], wh[x], wl[x]);
            uint4* dh = (uint4*)&sm.khi[w][lane][0];
            dh[0] = make_uint4(wh[0], wh[4], wh[1], wh[5]);
            dh[1] = make_uint4(wh[2], wh[6], wh[3], wh[7]);
            uint4* dl = (uint4*)&sm.klo[w][lane][0];
            dl[0] = make_uint4(wl[0], wl[4], wl[1], wl[5]);
            dl[1] = make_uint4(wl[2], wl[6], wl[3], wl[7]);
        }
        {   // V: thread owns (chunk vjt, d-col vn); reads 16 consecutive keys
            float f[16];
            #pragma unroll
            for (int kk = 0; kk < 16; kk++) f[kk] = sm.u.r.vraw[16 * vjt + kk][vn];
            uint32_t wh[8], wl[8];
            #pragma unroll
            for (int x = 0; x < 8; x++) split2(f[2 * x], f[2 * x + 1], wh[x], wl[x]);
            uint4* dh = (uint4*)&sm.vhi[vjt][vn][0];
            dh[0] = make_uint4(wh[0], wh[4], wh[1], wh[5]);
            dh[1] = make_uint4(wh[2], wh[6], wh[3], wh[7]);
            uint4* dl = (uint4*)&sm.vlo[vjt][vn][0];
            dl[0] = make_uint4(wl[0], wl[4], wl[1], wl[5]);
            dl[1] = make_uint4(wl[2], wl[6], wl[3], wl[7]);
        }
    };

    auto compute = [&](int t) {
        const int j0 = 32 * t;
        if (j0 > qb * 64 + w * 16 + 15) return;   // warp-uniform: fully masked

        // ---- S = Q K^T, bf16x3 ----
        float sacc[4][4];
        #pragma unroll
        for (int nt = 0; nt < 4; nt++)
            #pragma unroll
            for (int i = 0; i < 4; i++) sacc[nt][i] = 0.f;
        #pragma unroll
        for (int kt = 0; kt < 4; kt++) {
            #pragma unroll
            for (int nt = 0; nt < 4; nt++) {
                uint2 bh = sm.khi[kt][8 * nt + r][c];
                uint2 bl = sm.klo[kt][8 * nt + r][c];
                mma_bf16(sacc[nt], qlo[kt], bh.x, bh.y);
                mma_bf16(sacc[nt], qhi[kt], bl.x, bl.y);
                mma_bf16(sacc[nt], qhi[kt], bh.x, bh.y);
            }
        }

        // ---- causal mask (diagonal tiles only) ----
        if (j0 + 31 > qb * 64 + w * 16) {
            #pragma unroll
            for (int nt = 0; nt < 4; nt++) {
                int col = j0 + 8 * nt + 2 * c;
                if (col     > row0) sacc[nt][0] = -1e30f;
                if (col + 1 > row0) sacc[nt][1] = -1e30f;
                if (col     > row1) sacc[nt][2] = -1e30f;
                if (col + 1 > row1) sacc[nt][3] = -1e30f;
            }
        }

        // ---- online softmax ----
        float mx0 = sacc[0][0], mx1 = sacc[0][2];
        #pragma unroll
        for (int nt = 0; nt < 4; nt++) {
            mx0 = fmaxf(mx0, fmaxf(sacc[nt][0], sacc[nt][1]));
            mx1 = fmaxf(mx1, fmaxf(sacc[nt][2], sacc[nt][3]));
        }
        mx0 = fmaxf(mx0, __shfl_xor_sync(0xffffffffu, mx0, 1));
        mx0 = fmaxf(mx0, __shfl_xor_sync(0xffffffffu, mx0, 2));
        mx1 = fmaxf(mx1, __shfl_xor_sync(0xffffffffu, mx1, 1));
        mx1 = fmaxf(mx1, __shfl_xor_sync(0xffffffffu, mx1, 2));

        const float nm0 = fmaxf(m0, mx0), nm1 = fmaxf(m1, mx1);
        const float cor0 = __expf(m0 - nm0), cor1 = __expf(m1 - nm1);
        l0 *= cor0; l1 *= cor1;
        #pragma unroll
        for (int nt = 0; nt < 8; nt++) {
            oacc[nt][0] *= cor0; oacc[nt][1] *= cor0;
            oacc[nt][2] *= cor1; oacc[nt][3] *= cor1;
        }

        uint32_t ph[4][2], pl[4][2];
        float sum0 = 0.f, sum1 = 0.f;
        #pragma unroll
        for (int nt = 0; nt < 4; nt++) {
            float p00 = __expf(sacc[nt][0] - nm0);
            float p01 = __expf(sacc[nt][1] - nm0);
            float p10 = __expf(sacc[nt][2] - nm1);
            float p11 = __expf(sacc[nt][3] - nm1);
            sum0 += p00 + p01; sum1 += p10 + p11;
            split2(p00, p01, ph[nt][0], pl[nt][0]);   // row r
            split2(p10, p11, ph[nt][1], pl[nt][1]);   // row r+8
        }
        sum0 += __shfl_xor_sync(0xffffffffu, sum0, 1);
        sum0 += __shfl_xor_sync(0xffffffffu, sum0, 2);
        sum1 += __shfl_xor_sync(0xffffffffu, sum1, 1);
        sum1 += __shfl_xor_sync(0xffffffffu, sum1, 2);
        l0 += sum0; l1 += sum1;
        m0 = nm0; m1 = nm1;

        // ---- O += P V, bf16x3 (P fragments straight from registers) ----
        #pragma unroll
        for (int jt = 0; jt < 2; jt++) {
            uint32_t ah[4] = {ph[2*jt][0], ph[2*jt][1], ph[2*jt+1][0], ph[2*jt+1][1]};
            uint32_t al[4] = {pl[2*jt][0], pl[2*jt][1], pl[2*jt+1][0], pl[2*jt+1][1]};
            #pragma unroll
            for (int nt = 0; nt < 8; nt++) {
                uint2 bh = sm.vhi[jt][8 * nt + r][c];
                uint2 bl = sm.vlo[jt][8 * nt + r][c];
                mma_bf16(oacc[nt], al, bh.x, bh.y);
                mma_bf16(oacc[nt], ah, bl.x, bl.y);
                mma_bf16(oacc[nt], ah, bh.x, bh.y);
            }
        }
    };

    const int ntile = 2 * (qb + 1);
    stage(0);
    asm volatile("cp.async.wait_group 0;" ::: "memory");
    __syncthreads();
    convert();
    __syncthreads();
    for (int t = 0; t < ntile; t++) {
        if (t + 1 < ntile) stage(t + 1);   // async loads overlap compute
        compute(t);
        if (t + 1 < ntile) {
            asm volatile("cp.async.wait_group 0;" ::: "memory");
            __syncthreads();
            convert();
            __syncthreads();
        }
    }

    // ---- epilogue ----
    const float inv0 = 1.f / l0, inv1 = 1.f / l1;
    float* o0 = out + ((size_t)h * SEQ + row0) * HDIM;
    float* o1 = out + ((size_t)h * SEQ + row1) * HDIM;
    #pragma unroll
    for (int nt = 0; nt < 8; nt++) {
        int col = 8 * nt + 2 * c;
        *(float2*)&o0[col] = make_float2(oacc[nt][0] * inv0, oacc[nt][1] * inv0);
        *(float2*)&o1[col] = make_float2(oacc[nt][2] * inv1, oacc[nt][3] * inv1);
    }
}

extern "C" void kernel_launch(void* const* d_in, const int* in_sizes, int n_in,
                              void* d_out, int out_size)
{
    const float* q = (const float*)d_in[0];
    const float* k = (const float*)d_in[1];
    const float* v = (const float*)d_in[2];
    float* out = (float*)d_out;

    dim3 grid(SEQ / 64, 16, 1);   // 64 query blocks x 16 heads
    attn_bf16x3_flash<<<grid, 128>>>(q, k, v, out);
}